// round 2
// baseline (speedup 1.0000x reference)
#include <cuda_runtime.h>
#include <float.h>

// Problem constants (from reference: B=32, C=64, H=W=64, code_size=512, BETA=0.25)
#define Bn   32
#define Cn   64
#define HWn  4096
#define CBn  512
#define ST_ELEMS  (Bn * Cn * HWn)   // 8388608
#define IDX_ELEMS (Bn * HWn)        // 131072
#define NBLOCKS   256
// smem: codebook 512*64 floats + cnorm 512 floats
#define SMEMSZ (CBn * Cn * 4 + CBn * 4)

typedef unsigned long long ull;

__device__ float g_blocksums[NBLOCKS];

static __device__ __forceinline__ void fma2(ull &acc, ull a, ull b) {
    asm("fma.rn.f32x2 %0, %1, %2, %0;" : "+l"(acc) : "l"(a), "l"(b));
}
static __device__ __forceinline__ ull pack2(float lo, float hi) {
    ull r; asm("mov.b64 %0, {%1, %2};" : "=l"(r) : "f"(lo), "f"(hi)); return r;
}
static __device__ __forceinline__ float2 unpack2(ull v) {
    float2 r; asm("mov.b64 {%0, %1}, %2;" : "=f"(r.x), "=f"(r.y) : "l"(v)); return r;
}

// Main kernel: one block = one (b, 512-wide hw tile). 256 threads, 2 rows/thread.
// Row n = hw*B + b of the reference's (N, C) matrix is inputs[b, :, hw].
__global__ void __launch_bounds__(256, 1) vq_main_kernel(
    const float* __restrict__ inp,   // (B, C, H, W)
    const float* __restrict__ cb,    // (512, 64)
    float* __restrict__ out,
    long long out_size)
{
    extern __shared__ float smem[];
    float* scb = smem;              // codebook, row-major 512x64
    float* scn = smem + CBn * Cn;   // per-code squared norms

    const int tid = threadIdx.x;

    // Cooperative codebook load into smem (float4).
    for (int i = tid; i < CBn * Cn / 4; i += 256)
        ((float4*)scb)[i] = ((const float4*)cb)[i];

    // Per-code norms from global (NEON-style 4-lane accumulate + pairwise combine).
    for (int j = tid; j < CBn; j += 256) {
        const float4* r = (const float4*)(cb + j * Cn);
        float sa = 0.f, sb = 0.f, sc = 0.f, sd = 0.f;
        #pragma unroll
        for (int i = 0; i < 16; i++) {
            float4 v = r[i];
            sa = fmaf(v.x, v.x, sa);
            sb = fmaf(v.y, v.y, sb);
            sc = fmaf(v.z, v.z, sc);
            sd = fmaf(v.w, v.w, sd);
        }
        scn[j] = (sa + sb) + (sc + sd);
    }
    __syncthreads();

    const int b      = blockIdx.x >> 3;
    const int hwbase = (blockIdx.x & 7) << 9;
    const int warp   = tid >> 5;
    const int lane   = tid & 31;
    const int hw0    = hwbase + (warp << 6) + lane;
    const int hw1    = hw0 + 32;

    const float* __restrict__ rowbase = inp + (size_t)b * Cn * HWn;

    // Load both rows into registers as f32x2 pairs (coalesced 128B per (c, warp)).
    ull x0[32], x1[32];
    #pragma unroll
    for (int i = 0; i < 32; i++) {
        x0[i] = pack2(rowbase[(size_t)(2 * i) * HWn + hw0],
                      rowbase[(size_t)(2 * i + 1) * HWn + hw0]);
        x1[i] = pack2(rowbase[(size_t)(2 * i) * HWn + hw1],
                      rowbase[(size_t)(2 * i + 1) * HWn + hw1]);
    }

    // Row squared norms, 4-lane pattern: lanes (4i..4i+3) -> (s01, s23).
    ull n0a = 0ULL, n0b = 0ULL, n1a = 0ULL, n1b = 0ULL;
    #pragma unroll
    for (int i = 0; i < 16; i++) {
        fma2(n0a, x0[2 * i],     x0[2 * i]);
        fma2(n0b, x0[2 * i + 1], x0[2 * i + 1]);
        fma2(n1a, x1[2 * i],     x1[2 * i]);
        fma2(n1b, x1[2 * i + 1], x1[2 * i + 1]);
    }
    float2 t0 = unpack2(n0a), t1 = unpack2(n0b);
    const float xx0 = (t0.x + t0.y) + (t1.x + t1.y);
    float2 t2 = unpack2(n1a), t3 = unpack2(n1b);
    const float xx1 = (t2.x + t2.y) + (t3.x + t3.y);

    // Argmin over 512 codes. dist = (xx - 2*dot) + cnorm, fp32, first-min wins.
    float best0 = FLT_MAX, best1 = FLT_MAX;
    int bj0 = 0, bj1 = 0;

    for (int j = 0; j < CBn; j++) {
        const ulonglong2* __restrict__ crow = (const ulonglong2*)(scb + j * Cn);
        ull a0 = 0ULL, a1 = 0ULL, c0 = 0ULL, c1 = 0ULL;
        #pragma unroll
        for (int i = 0; i < 16; i++) {
            ulonglong2 cc = crow[i];     // broadcast LDS.128 (all lanes same addr)
            fma2(a0, x0[2 * i],     cc.x);
            fma2(a1, x0[2 * i + 1], cc.y);
            fma2(c0, x1[2 * i],     cc.x);
            fma2(c1, x1[2 * i + 1], cc.y);
        }
        float2 pa = unpack2(a0), pb = unpack2(a1);
        float dot0 = (pa.x + pa.y) + (pb.x + pb.y);
        float2 qa = unpack2(c0), qb = unpack2(c1);
        float dot1 = (qa.x + qa.y) + (qb.x + qb.y);

        float cn = scn[j];
        float d0 = (xx0 - 2.0f * dot0) + cn;
        float d1 = (xx1 - 2.0f * dot1) + cn;
        if (d0 < best0) { best0 = d0; bj0 = j; }
        if (d1 < best1) { best1 = d1; bj1 = j; }
    }

    // Epilogue: gather winning code rows from GLOBAL (L2-resident; avoids the
    // 32-way smem bank conflicts the per-lane-random gather would cause),
    // write st, accumulate loss partials.
    float lsum = 0.f;
    {
        float* st0 = out + (size_t)b * Cn * HWn + hw0;
        float* st1 = out + (size_t)b * Cn * HWn + hw1;
        const float4* c0r = (const float4*)(cb + bj0 * Cn);
        const float4* c1r = (const float4*)(cb + bj1 * Cn);
        #pragma unroll
        for (int i = 0; i < 16; i++) {
            float4 v0 = c0r[i];
            float4 v1 = c1r[i];
            float2 xa0 = unpack2(x0[2 * i]);
            float2 xb0 = unpack2(x0[2 * i + 1]);
            float2 xa1 = unpack2(x1[2 * i]);
            float2 xb1 = unpack2(x1[2 * i + 1]);

            st0[(size_t)(4 * i + 0) * HWn] = v0.x;
            st0[(size_t)(4 * i + 1) * HWn] = v0.y;
            st0[(size_t)(4 * i + 2) * HWn] = v0.z;
            st0[(size_t)(4 * i + 3) * HWn] = v0.w;

            st1[(size_t)(4 * i + 0) * HWn] = v1.x;
            st1[(size_t)(4 * i + 1) * HWn] = v1.y;
            st1[(size_t)(4 * i + 2) * HWn] = v1.z;
            st1[(size_t)(4 * i + 3) * HWn] = v1.w;

            float e;
            e = v0.x - xa0.x; lsum = fmaf(e, e, lsum);
            e = v0.y - xa0.y; lsum = fmaf(e, e, lsum);
            e = v0.z - xb0.x; lsum = fmaf(e, e, lsum);
            e = v0.w - xb0.y; lsum = fmaf(e, e, lsum);
            e = v1.x - xa1.x; lsum = fmaf(e, e, lsum);
            e = v1.y - xa1.y; lsum = fmaf(e, e, lsum);
            e = v1.z - xb1.x; lsum = fmaf(e, e, lsum);
            e = v1.w - xb1.y; lsum = fmaf(e, e, lsum);
        }
    }

    // Indices (as float) at offset ST_ELEMS, layout (B, HW).
    {
        long long p0 = (long long)ST_ELEMS + (long long)b * HWn + hw0;
        long long p1 = p0 + 32;
        if (p0 < out_size) out[p0] = (float)bj0;
        if (p1 < out_size) out[p1] = (float)bj1;
    }

    // Deterministic block reduction of loss partials (fixed tree order).
    #pragma unroll
    for (int off = 16; off > 0; off >>= 1)
        lsum += __shfl_down_sync(0xffffffffu, lsum, off);
    __shared__ float wsum[8];
    if (lane == 0) wsum[warp] = lsum;
    __syncthreads();
    if (tid == 0) {
        float s = 0.f;
        #pragma unroll
        for (int w = 0; w < 8; w++) s += wsum[w];
        g_blocksums[blockIdx.x] = s;
    }
}

// Final: deterministic sum of block partials, loss = (1 + BETA) * MSE.
__global__ void vq_finish_kernel(float* __restrict__ out, long long out_size) {
    if (threadIdx.x == 0 && blockIdx.x == 0) {
        double s = 0.0;
        for (int i = 0; i < NBLOCKS; i++) s += (double)g_blocksums[i];
        double mse = s / (double)ST_ELEMS;
        long long off = (long long)ST_ELEMS + IDX_ELEMS;
        if (off < out_size) out[off] = (float)(1.25 * mse);
    }
}

extern "C" void kernel_launch(void* const* d_in, const int* in_sizes, int n_in,
                              void* d_out, int out_size) {
    const float* inp = (const float*)d_in[0];
    const float* cb  = (const float*)d_in[1];
    // Defensive: metadata order should be (inputs, codebook); swap if sizes say otherwise.
    if (n_in >= 2 && in_sizes[0] == CBn * Cn && in_sizes[1] == ST_ELEMS) {
        const float* t = inp; inp = cb; cb = t;
    }

    cudaFuncSetAttribute(vq_main_kernel,
                         cudaFuncAttributeMaxDynamicSharedMemorySize, SMEMSZ);

    vq_main_kernel<<<NBLOCKS, 256, SMEMSZ>>>(inp, cb, (float*)d_out,
                                             (long long)out_size);
    vq_finish_kernel<<<1, 32>>>((float*)d_out, (long long)out_size);
}